// round 10
// baseline (speedup 1.0000x reference)
#include <cuda_runtime.h>
#include <cstdint>

#define Bt   128
#define Tt   512
#define Et   256
#define Ht   512
#define VCt  64
#define VPt  128
#define NCTA 128

// ---------------- persistent device scratch ----------------
__device__ float g_P[VCt * Ht];
__device__ float g_h0[2][Ht * Bt];   // [j][b]
__device__ float g_h1[2][Ht * Bt];
__device__ float g_ysT[(size_t)Tt * Ht * Bt];
__device__ volatile unsigned g_flags[NCTA];

// ---------------- kernel 0: reset barrier flags (runs before rec_kernel) ----
__global__ void reset_kernel() { g_flags[threadIdx.x] = 0u; }

// ---------------- kernel 1: P = emb_table @ W_xh0 + b_xh0 ----------------
__global__ __launch_bounds__(128) void proj_kernel(
    const float* __restrict__ emb, const float* __restrict__ Wxh0,
    const float* __restrict__ bxh0) {
  __shared__ float esh[Et];
  int v = blockIdx.x;
  for (int i = threadIdx.x; i < Et; i += 128) esh[i] = emb[v * Et + i];
  __syncthreads();
  int j = threadIdx.x + blockIdx.y * 128;
  float s = bxh0[j];
#pragma unroll 8
  for (int e = 0; e < Et; ++e) s = fmaf(esh[e], Wxh0[e * Ht + j], s);
  g_P[v * Ht + j] = s;
}

__device__ __forceinline__ void fma16(float4& a0, float4& a1, float4& a2,
                                      float4& a3, const float4 w,
                                      const float4 hv) {
  a0.x = fmaf(w.x, hv.x, a0.x); a0.y = fmaf(w.x, hv.y, a0.y);
  a0.z = fmaf(w.x, hv.z, a0.z); a0.w = fmaf(w.x, hv.w, a0.w);
  a1.x = fmaf(w.y, hv.x, a1.x); a1.y = fmaf(w.y, hv.y, a1.y);
  a1.z = fmaf(w.y, hv.z, a1.z); a1.w = fmaf(w.y, hv.w, a1.w);
  a2.x = fmaf(w.z, hv.x, a2.x); a2.y = fmaf(w.z, hv.y, a2.y);
  a2.z = fmaf(w.z, hv.z, a2.z); a2.w = fmaf(w.z, hv.w, a2.w);
  a3.x = fmaf(w.w, hv.x, a3.x); a3.y = fmaf(w.w, hv.y, a3.y);
  a3.z = fmaf(w.w, hv.z, a3.z); a3.w = fmaf(w.w, hv.w, a3.w);
}

// ---------------- kernel 2: persistent recurrent kernel ----------------
// 128 CTAs, CTA owns cols jb..jb+3 of h0 AND h1. One flag-allgather barrier
// per step. Per step (h0(t) published): compute h1(t) AND pre-activation of
// h0(t+1), sharing the single load of h0(t).
__global__ __launch_bounds__(256, 1) void rec_kernel(
    const int* __restrict__ src, const int* __restrict__ lens,
    const float* __restrict__ Whh0, const float* __restrict__ Wxh1,
    const float* __restrict__ bxh1, const float* __restrict__ Whh1) {
  extern __shared__ char dsm[];
  float4* Wsh0 = (float4*)dsm;         // [512 k]{c0..c3}  8 KB (Whh0)
  float4* Wsh1 = Wsh0 + Ht;            // Wxh1
  float4* Wsh2 = Wsh1 + Ht;            // Whh1
  float4* red4 = Wsh2 + Ht;            // [8 s][8 g][32 bt] 32 KB
  float* Psh = (float*)(red4 + 2048);  // [64 v][4 c]  1 KB

  __shared__ int srcsh[Bt];
  __shared__ int lensh[Bt];
  __shared__ float bsh[4];

  const int tid = threadIdx.x;
  const int cta = blockIdx.x;
  const int jb = cta * 4;
  unsigned epoch = 0;

  for (int i = tid; i < Ht * 4; i += 256) {
    int k = i >> 2, c = i & 3;
    ((float*)Wsh0)[i] = Whh0[k * Ht + jb + c];
    ((float*)Wsh1)[i] = Wxh1[k * Ht + jb + c];
    ((float*)Wsh2)[i] = Whh1[k * Ht + jb + c];
  }
  for (int i = tid; i < VCt * 4; i += 256) {
    int v = i >> 2, c = i & 3;
    Psh[i] = g_P[v * Ht + jb + c];
  }
  if (tid < Bt) lensh[tid] = lens[tid];
  if (tid < 4) bsh[tid] = bxh1[jb + tid];
  // h1(-1) = 0 in buffer 1 (own cols only)
  for (int i = tid; i < 512; i += 256) {
    int c = i >> 7, b = i & 127;
    g_h1[1][(jb + c) * Bt + b] = 0.f;
  }
  __syncthreads();
  // prologue: h0(0) = mask0 ? tanh(P[tok0]) : 0  -> buffer 0
  for (int i = tid; i < 512; i += 256) {
    int c = i >> 7, b = i & 127;
    int tok = src[b * Tt];
    float a = Psh[tok * 4 + c];
    g_h0[0][(jb + c) * Bt + b] = (0 < lensh[b]) ? tanhf(a) : 0.f;
  }

  // flag-allgather grid barrier: warp 0 arrives + waits on all 128 flags
#define GBAR()                                                  \
  do {                                                          \
    __syncthreads();                                            \
    ++epoch;                                                    \
    if (tid < 32) {                                             \
      if (tid == 0) {                                           \
        __threadfence();                                        \
        g_flags[cta] = epoch;                                   \
      }                                                         \
      int i0 = tid * 4;                                         \
      while (g_flags[i0] < epoch) __nanosleep(20);              \
      while (g_flags[i0 + 1] < epoch) __nanosleep(20);          \
      while (g_flags[i0 + 2] < epoch) __nanosleep(20);          \
      while (g_flags[i0 + 3] < epoch) __nanosleep(20);          \
      if (tid == 0) __threadfence();                            \
    }                                                           \
    __syncthreads();                                            \
  } while (0)

  GBAR();  // h0(0), h1(-1) visible everywhere

  const int bt = tid & 31;   // 4 b's: b = 4*bt .. 4*bt+3
  const int s = tid >> 5;    // k-slice of 64

  for (int t = 0; t < Tt; ++t) {
    const int p = t & 1;
    const float4* H0 = (const float4*)g_h0[p];        // h0(t)
    const float4* H1p = (const float4*)g_h1[p ^ 1];   // h1(t-1)
    float* h0n = g_h0[p ^ 1];                         // h0(t+1)
    float* h1c = g_h1[p];                             // h1(t)

    if (tid < Bt) {
      int tn = (t + 1 < Tt) ? t + 1 : Tt - 1;
      srcsh[tid] = src[tid * Tt + tn];
    }

    // ---- fused GEMMs: accN = h0(t)@Whh0 ; accO = h0(t)@Wxh1 + h1(t-1)@Whh1
    {
      float4 z = make_float4(0, 0, 0, 0);
      float4 n0 = z, n1 = z, n2 = z, n3 = z;
      float4 o0 = z, o1 = z, o2 = z, o3 = z;
#pragma unroll 4
      for (int kk = 0; kk < 64; ++kk) {
        int k = s * 64 + kk;
        float4 ha = H0[k * 32 + bt];
        float4 hb = H1p[k * 32 + bt];
        float4 w0 = Wsh0[k];
        float4 w1 = Wsh1[k];
        float4 w2 = Wsh2[k];
        fma16(n0, n1, n2, n3, w0, ha);
        fma16(o0, o1, o2, o3, w1, ha);
        fma16(o0, o1, o2, o3, w2, hb);
      }
      red4[s * 256 + 0 * 32 + bt] = n0;
      red4[s * 256 + 1 * 32 + bt] = n1;
      red4[s * 256 + 2 * 32 + bt] = n2;
      red4[s * 256 + 3 * 32 + bt] = n3;
      red4[s * 256 + 4 * 32 + bt] = o0;
      red4[s * 256 + 5 * 32 + bt] = o1;
      red4[s * 256 + 6 * 32 + bt] = o2;
      red4[s * 256 + 7 * 32 + bt] = o3;
    }
    __syncthreads();

    // ---- reduce: thread tid -> group g (phase*4+c), bt2, 4 b's ----
    {
      int g = tid >> 5, bt2 = tid & 31;
      int b0 = bt2 * 4;
      float4 sm = red4[g * 32 + bt2];
#pragma unroll
      for (int s2 = 1; s2 < 8; ++s2) {
        float4 r = red4[s2 * 256 + g * 32 + bt2];
        sm.x += r.x; sm.y += r.y; sm.z += r.z; sm.w += r.w;
      }
      int l0 = lensh[b0], l1 = lensh[b0 + 1], l2 = lensh[b0 + 2],
          l3 = lensh[b0 + 3];
      if (g < 4) {  // h0(t+1)
        int c = g;
        sm.x += Psh[srcsh[b0] * 4 + c];
        sm.y += Psh[srcsh[b0 + 1] * 4 + c];
        sm.z += Psh[srcsh[b0 + 2] * 4 + c];
        sm.w += Psh[srcsh[b0 + 3] * 4 + c];
        const float* h0cur = g_h0[p];
        float4 prev = *(const float4*)&h0cur[(jb + c) * Bt + b0];
        float4 nv;
        nv.x = (t + 1 < l0) ? tanhf(sm.x) : prev.x;
        nv.y = (t + 1 < l1) ? tanhf(sm.y) : prev.y;
        nv.z = (t + 1 < l2) ? tanhf(sm.z) : prev.z;
        nv.w = (t + 1 < l3) ? tanhf(sm.w) : prev.w;
        *(float4*)&h0n[(jb + c) * Bt + b0] = nv;
      } else {  // h1(t) + ys(t)
        int c = g - 4;
        float bv = bsh[c];
        sm.x += bv; sm.y += bv; sm.z += bv; sm.w += bv;
        const float* h1prv = g_h1[p ^ 1];
        float4 prev = *(const float4*)&h1prv[(jb + c) * Bt + b0];
        float4 nv;
        nv.x = (t < l0) ? tanhf(sm.x) : prev.x;
        nv.y = (t < l1) ? tanhf(sm.y) : prev.y;
        nv.z = (t < l2) ? tanhf(sm.z) : prev.z;
        nv.w = (t < l3) ? tanhf(sm.w) : prev.w;
        *(float4*)&h1c[(jb + c) * Bt + b0] = nv;
        float* ys = g_ysT + (size_t)t * (Ht * Bt);
        *(float4*)&ys[(jb + c) * Bt + b0] = nv;
      }
    }
    GBAR();  // publish h0(t+1), h1(t), ys(t); protects red/srcsh reuse
  }
#undef GBAR
}

// ---------------- kernel 3: logits = ys @ fc_w + fc_b ----------------
__global__ __launch_bounds__(256) void fc_kernel(const float* __restrict__ fcw,
                                                 const float* __restrict__ fcb,
                                                 float* __restrict__ out) {
  __shared__ float4 Ash[32 * 32];
  __shared__ float4 Bsh[32 * 16];
  const int t = blockIdx.y;
  const int pt = blockIdx.x;
  const int tid = threadIdx.x;
  const int pq = tid & 15;
  const int bq = tid >> 4;
  const float4* ys4 = (const float4*)g_ysT + (size_t)t * (Ht * Bt / 4);
  const float4* w4 = (const float4*)fcw;

  float4 acc[8];
#pragma unroll
  for (int i = 0; i < 8; ++i) acc[i] = make_float4(0, 0, 0, 0);

  for (int k0 = 0; k0 < Ht; k0 += 32) {
#pragma unroll
    for (int i = 0; i < 4; ++i) {
      int idx = tid + i * 256;
      int kk = idx >> 5, b4 = idx & 31;
      Ash[idx] = ys4[(k0 + kk) * 32 + b4];
    }
#pragma unroll
    for (int i = 0; i < 2; ++i) {
      int idx = tid + i * 256;
      int kk = idx >> 4, p4 = idx & 15;
      Bsh[idx] = w4[(k0 + kk) * (VPt / 4) + pt * 16 + p4];
    }
    __syncthreads();
#pragma unroll
    for (int kk = 0; kk < 32; ++kk) {
      float4 wv = Bsh[kk * 16 + pq];
      float4 hA = Ash[kk * 32 + bq * 2];
      float4 hB = Ash[kk * 32 + bq * 2 + 1];
      float hb[8] = {hA.x, hA.y, hA.z, hA.w, hB.x, hB.y, hB.z, hB.w};
#pragma unroll
      for (int i = 0; i < 8; ++i) {
        acc[i].x = fmaf(hb[i], wv.x, acc[i].x);
        acc[i].y = fmaf(hb[i], wv.y, acc[i].y);
        acc[i].z = fmaf(hb[i], wv.z, acc[i].z);
        acc[i].w = fmaf(hb[i], wv.w, acc[i].w);
      }
    }
    __syncthreads();
  }
  float4 bv = ((const float4*)fcb)[pt * 16 + pq];
  float4* out4 = (float4*)out;
#pragma unroll
  for (int i = 0; i < 8; ++i) {
    int b = bq * 8 + i;
    float4 v;
    v.x = acc[i].x + bv.x;
    v.y = acc[i].y + bv.y;
    v.z = acc[i].z + bv.z;
    v.w = acc[i].w + bv.w;
    out4[((size_t)b * Tt + t) * (VPt / 4) + pt * 16 + pq] = v;
  }
}

extern "C" void kernel_launch(void* const* d_in, const int* in_sizes, int n_in,
                              void* d_out, int out_size) {
  const int* src = (const int*)d_in[0];
  const int* lens = (const int*)d_in[1];
  const float* emb = (const float*)d_in[2];
  const float* Wxh0 = (const float*)d_in[3];
  const float* bxh0 = (const float*)d_in[4];
  const float* Whh0 = (const float*)d_in[5];
  const float* Wxh1 = (const float*)d_in[6];
  const float* bxh1 = (const float*)d_in[7];
  const float* Whh1 = (const float*)d_in[8];
  const float* fcw = (const float*)d_in[9];
  const float* fcb = (const float*)d_in[10];

  const int smem_bytes = 3 * 8192 + 32768 + 1024;  // 57344
  cudaFuncSetAttribute(rec_kernel, cudaFuncAttributeMaxDynamicSharedMemorySize,
                       smem_bytes);

  reset_kernel<<<1, NCTA>>>();
  proj_kernel<<<dim3(VCt, 4), 128>>>(emb, Wxh0, bxh0);
  rec_kernel<<<NCTA, 256, smem_bytes>>>(src, lens, Whh0, Wxh1, bxh1, Whh1);
  fc_kernel<<<dim3(2, Tt), 256>>>(fcw, fcb, (float*)d_out);
}

// round 12
// speedup vs baseline: 1.4054x; 1.4054x over previous
#include <cuda_runtime.h>
#include <cstdint>

#define Bt   128
#define Tt   512
#define Et   256
#define Ht   512
#define VCt  64
#define VPt  128
#define NCTA 128

// ---------------- persistent device scratch ----------------
__device__ float g_P[VCt * Ht];
__device__ float g_h0[2][Ht * Bt];   // [j][b]
__device__ float g_h1[2][Ht * Bt];
__device__ float g_ysT[(size_t)Tt * Ht * Bt];
// hierarchical barrier state (monotonic; reset before each rec launch)
__device__ unsigned g_gcnt[8 * 32];    // 8 group counters, 128B apart
__device__ unsigned g_rootcnt;
__device__ volatile unsigned g_sense;

// ---------------- kernel 0: reset barrier state ----------------
__global__ void reset_kernel() {
  int i = threadIdx.x;
  if (i < 8 * 32) g_gcnt[i] = 0u;
  if (i == 0) { g_rootcnt = 0u; g_sense = 0u; }
}

// ---------------- kernel 1: P = emb_table @ W_xh0 + b_xh0 ----------------
__global__ __launch_bounds__(128) void proj_kernel(
    const float* __restrict__ emb, const float* __restrict__ Wxh0,
    const float* __restrict__ bxh0) {
  __shared__ float esh[Et];
  int v = blockIdx.x;
  for (int i = threadIdx.x; i < Et; i += 128) esh[i] = emb[v * Et + i];
  __syncthreads();
  int j = threadIdx.x + blockIdx.y * 128;
  float s = bxh0[j];
#pragma unroll 8
  for (int e = 0; e < Et; ++e) s = fmaf(esh[e], Wxh0[e * Ht + j], s);
  g_P[v * Ht + j] = s;
}

__device__ __forceinline__ void fma16(float4& a0, float4& a1, float4& a2,
                                      float4& a3, const float4 w,
                                      const float4 hv) {
  a0.x = fmaf(w.x, hv.x, a0.x); a0.y = fmaf(w.x, hv.y, a0.y);
  a0.z = fmaf(w.x, hv.z, a0.z); a0.w = fmaf(w.x, hv.w, a0.w);
  a1.x = fmaf(w.y, hv.x, a1.x); a1.y = fmaf(w.y, hv.y, a1.y);
  a1.z = fmaf(w.y, hv.z, a1.z); a1.w = fmaf(w.y, hv.w, a1.w);
  a2.x = fmaf(w.z, hv.x, a2.x); a2.y = fmaf(w.z, hv.y, a2.y);
  a2.z = fmaf(w.z, hv.z, a2.z); a2.w = fmaf(w.z, hv.w, a2.w);
  a3.x = fmaf(w.w, hv.x, a3.x); a3.y = fmaf(w.w, hv.y, a3.y);
  a3.z = fmaf(w.w, hv.z, a3.z); a3.w = fmaf(w.w, hv.w, a3.w);
}

// ---------------- kernel 2: persistent recurrent kernel ----------------
// 128 CTAs, CTA owns cols jb..jb+3 of h0 AND h1. One grid barrier per step
// (two-level atomic tree arrival, single-poller sense wait). Per step (h0(t)
// published): compute h1(t) AND pre-activation of h0(t+1) sharing one h0 load.
__global__ __launch_bounds__(256, 1) void rec_kernel(
    const int* __restrict__ src, const int* __restrict__ lens,
    const float* __restrict__ Whh0, const float* __restrict__ Wxh1,
    const float* __restrict__ bxh1, const float* __restrict__ Whh1) {
  extern __shared__ char dsm[];
  float4* Wsh0 = (float4*)dsm;         // [512 k]{c0..c3}  8 KB (Whh0)
  float4* Wsh1 = Wsh0 + Ht;            // Wxh1
  float4* Wsh2 = Wsh1 + Ht;            // Whh1
  float4* red4 = Wsh2 + Ht;            // [8 s][8 g][32 bt] 32 KB
  float* Psh = (float*)(red4 + 2048);  // [64 v][4 c]  1 KB

  __shared__ int srcsh[Bt];
  __shared__ int lensh[Bt];
  __shared__ float bsh[4];

  const int tid = threadIdx.x;
  const int cta = blockIdx.x;
  const int jb = cta * 4;
  const int grp = cta >> 4;            // 8 groups of 16 CTAs
  unsigned epoch = 0;

  for (int i = tid; i < Ht * 4; i += 256) {
    int k = i >> 2, c = i & 3;
    ((float*)Wsh0)[i] = Whh0[k * Ht + jb + c];
    ((float*)Wsh1)[i] = Wxh1[k * Ht + jb + c];
    ((float*)Wsh2)[i] = Whh1[k * Ht + jb + c];
  }
  for (int i = tid; i < VCt * 4; i += 256) {
    int v = i >> 2, c = i & 3;
    Psh[i] = g_P[v * Ht + jb + c];
  }
  if (tid < Bt) lensh[tid] = lens[tid];
  if (tid < 4) bsh[tid] = bxh1[jb + tid];
  // h1(-1) = 0 in buffer 1 (own cols only)
  for (int i = tid; i < 512; i += 256) {
    int c = i >> 7, b = i & 127;
    g_h1[1][(jb + c) * Bt + b] = 0.f;
  }
  __syncthreads();
  // prologue: h0(0) = mask0 ? tanh(P[tok0]) : 0  -> buffer 0
  for (int i = tid; i < 512; i += 256) {
    int c = i >> 7, b = i & 127;
    int tok = src[b * Tt];
    float a = Psh[tok * 4 + c];
    g_h0[0][(jb + c) * Bt + b] = (0 < lensh[b]) ? tanhf(a) : 0.f;
  }

  // two-level atomic-tree grid barrier; one poller per CTA
#define GBAR()                                                        \
  do {                                                                \
    __syncthreads();                                                  \
    ++epoch;                                                          \
    if (tid == 0) {                                                   \
      __threadfence();                                                \
      unsigned o = atomicAdd(&g_gcnt[grp * 32], 1u);                  \
      if ((o & 15u) == 15u) {                                         \
        __threadfence();                                              \
        unsigned r = atomicAdd(&g_rootcnt, 1u);                       \
        if ((r & 7u) == 7u) {                                         \
          __threadfence();                                            \
          g_sense = epoch;                                            \
        }                                                             \
      }                                                               \
      while (g_sense < epoch) __nanosleep(20);                        \
      __threadfence();                                                \
    }                                                                 \
    __syncthreads();                                                  \
  } while (0)

  GBAR();  // h0(0), h1(-1) visible everywhere

  const int bt = tid & 31;   // 4 b's: b = 4*bt .. 4*bt+3
  const int s = tid >> 5;    // k-slice of 64

  // register-carried "previous value" for the masked freeze:
  // thread g<4 owns h0[jb+g][4*bt2..+3]; thread g>=4 owns h1[jb+g-4][...]
  float4 prevReg;
  {
    int g = tid >> 5, bt2 = tid & 31, b0 = bt2 * 4;
    if (g < 4)
      prevReg = *(const float4*)&g_h0[0][(jb + g) * Bt + b0];   // h0(0)
    else
      prevReg = make_float4(0.f, 0.f, 0.f, 0.f);                // h1(-1)
  }

  for (int t = 0; t < Tt; ++t) {
    const int p = t & 1;
    const float4* H0 = (const float4*)g_h0[p];        // h0(t)
    const float4* H1p = (const float4*)g_h1[p ^ 1];   // h1(t-1)
    float* h0n = g_h0[p ^ 1];                         // h0(t+1)
    float* h1c = g_h1[p];                             // h1(t)

    if (tid < Bt) {
      int tn = (t + 1 < Tt) ? t + 1 : Tt - 1;
      srcsh[tid] = src[tid * Tt + tn];
    }

    // ---- fused GEMMs: accN = h0(t)@Whh0 ; accO = h0(t)@Wxh1 + h1(t-1)@Whh1
    {
      float4 z = make_float4(0, 0, 0, 0);
      float4 n0 = z, n1 = z, n2 = z, n3 = z;
      float4 o0 = z, o1 = z, o2 = z, o3 = z;
#pragma unroll 4
      for (int kk = 0; kk < 64; ++kk) {
        int k = s * 64 + kk;
        float4 ha = H0[k * 32 + bt];
        float4 hb = H1p[k * 32 + bt];
        float4 w0 = Wsh0[k];
        float4 w1 = Wsh1[k];
        float4 w2 = Wsh2[k];
        fma16(n0, n1, n2, n3, w0, ha);
        fma16(o0, o1, o2, o3, w1, ha);
        fma16(o0, o1, o2, o3, w2, hb);
      }
      red4[s * 256 + 0 * 32 + bt] = n0;
      red4[s * 256 + 1 * 32 + bt] = n1;
      red4[s * 256 + 2 * 32 + bt] = n2;
      red4[s * 256 + 3 * 32 + bt] = n3;
      red4[s * 256 + 4 * 32 + bt] = o0;
      red4[s * 256 + 5 * 32 + bt] = o1;
      red4[s * 256 + 6 * 32 + bt] = o2;
      red4[s * 256 + 7 * 32 + bt] = o3;
    }
    __syncthreads();

    // ---- reduce: thread tid -> group g (phase*4+c), bt2, 4 b's ----
    {
      int g = tid >> 5, bt2 = tid & 31;
      int b0 = bt2 * 4;
      float4 sm = red4[g * 32 + bt2];
#pragma unroll
      for (int s2 = 1; s2 < 8; ++s2) {
        float4 r = red4[s2 * 256 + g * 32 + bt2];
        sm.x += r.x; sm.y += r.y; sm.z += r.z; sm.w += r.w;
      }
      int l0 = lensh[b0], l1 = lensh[b0 + 1], l2 = lensh[b0 + 2],
          l3 = lensh[b0 + 3];
      if (g < 4) {  // h0(t+1)
        int c = g;
        sm.x += Psh[srcsh[b0] * 4 + c];
        sm.y += Psh[srcsh[b0 + 1] * 4 + c];
        sm.z += Psh[srcsh[b0 + 2] * 4 + c];
        sm.w += Psh[srcsh[b0 + 3] * 4 + c];
        float4 nv;
        nv.x = (t + 1 < l0) ? tanhf(sm.x) : prevReg.x;
        nv.y = (t + 1 < l1) ? tanhf(sm.y) : prevReg.y;
        nv.z = (t + 1 < l2) ? tanhf(sm.z) : prevReg.z;
        nv.w = (t + 1 < l3) ? tanhf(sm.w) : prevReg.w;
        prevReg = nv;
        *(float4*)&h0n[(jb + c) * Bt + b0] = nv;
      } else {  // h1(t) + ys(t)
        int c = g - 4;
        float bv = bsh[c];
        sm.x += bv; sm.y += bv; sm.z += bv; sm.w += bv;
        float4 nv;
        nv.x = (t < l0) ? tanhf(sm.x) : prevReg.x;
        nv.y = (t < l1) ? tanhf(sm.y) : prevReg.y;
        nv.z = (t < l2) ? tanhf(sm.z) : prevReg.z;
        nv.w = (t < l3) ? tanhf(sm.w) : prevReg.w;
        prevReg = nv;
        *(float4*)&h1c[(jb + c) * Bt + b0] = nv;
        float* ys = g_ysT + (size_t)t * (Ht * Bt);
        *(float4*)&ys[(jb + c) * Bt + b0] = nv;
      }
    }
    GBAR();  // publish h0(t+1), h1(t), ys(t); protects red/srcsh reuse
  }
#undef GBAR
}

// ---------------- kernel 3: logits = ys @ fc_w + fc_b ----------------
__global__ __launch_bounds__(256) void fc_kernel(const float* __restrict__ fcw,
                                                 const float* __restrict__ fcb,
                                                 float* __restrict__ out) {
  __shared__ float4 Ash[32 * 32];
  __shared__ float4 Bsh[32 * 16];
  const int t = blockIdx.y;
  const int pt = blockIdx.x;
  const int tid = threadIdx.x;
  const int pq = tid & 15;
  const int bq = tid >> 4;
  const float4* ys4 = (const float4*)g_ysT + (size_t)t * (Ht * Bt / 4);
  const float4* w4 = (const float4*)fcw;

  float4 acc[8];
#pragma unroll
  for (int i = 0; i < 8; ++i) acc[i] = make_float4(0, 0, 0, 0);

  for (int k0 = 0; k0 < Ht; k0 += 32) {
#pragma unroll
    for (int i = 0; i < 4; ++i) {
      int idx = tid + i * 256;
      int kk = idx >> 5, b4 = idx & 31;
      Ash[idx] = ys4[(k0 + kk) * 32 + b4];
    }
#pragma unroll
    for (int i = 0; i < 2; ++i) {
      int idx = tid + i * 256;
      int kk = idx >> 4, p4 = idx & 15;
      Bsh[idx] = w4[(k0 + kk) * (VPt / 4) + pt * 16 + p4];
    }
    __syncthreads();
#pragma unroll
    for (int kk = 0; kk < 32; ++kk) {
      float4 wv = Bsh[kk * 16 + pq];
      float4 hA = Ash[kk * 32 + bq * 2];
      float4 hB = Ash[kk * 32 + bq * 2 + 1];
      float hb[8] = {hA.x, hA.y, hA.z, hA.w, hB.x, hB.y, hB.z, hB.w};
#pragma unroll
      for (int i = 0; i < 8; ++i) {
        acc[i].x = fmaf(hb[i], wv.x, acc[i].x);
        acc[i].y = fmaf(hb[i], wv.y, acc[i].y);
        acc[i].z = fmaf(hb[i], wv.z, acc[i].z);
        acc[i].w = fmaf(hb[i], wv.w, acc[i].w);
      }
    }
    __syncthreads();
  }
  float4 bv = ((const float4*)fcb)[pt * 16 + pq];
  float4* out4 = (float4*)out;
#pragma unroll
  for (int i = 0; i < 8; ++i) {
    int b = bq * 8 + i;
    float4 v;
    v.x = acc[i].x + bv.x;
    v.y = acc[i].y + bv.y;
    v.z = acc[i].z + bv.z;
    v.w = acc[i].w + bv.w;
    out4[((size_t)b * Tt + t) * (VPt / 4) + pt * 16 + pq] = v;
  }
}

extern "C" void kernel_launch(void* const* d_in, const int* in_sizes, int n_in,
                              void* d_out, int out_size) {
  const int* src = (const int*)d_in[0];
  const int* lens = (const int*)d_in[1];
  const float* emb = (const float*)d_in[2];
  const float* Wxh0 = (const float*)d_in[3];
  const float* bxh0 = (const float*)d_in[4];
  const float* Whh0 = (const float*)d_in[5];
  const float* Wxh1 = (const float*)d_in[6];
  const float* bxh1 = (const float*)d_in[7];
  const float* Whh1 = (const float*)d_in[8];
  const float* fcw = (const float*)d_in[9];
  const float* fcb = (const float*)d_in[10];

  const int smem_bytes = 3 * 8192 + 32768 + 1024;  // 57344
  cudaFuncSetAttribute(rec_kernel, cudaFuncAttributeMaxDynamicSharedMemorySize,
                       smem_bytes);

  reset_kernel<<<1, 256>>>();
  proj_kernel<<<dim3(VCt, 4), 128>>>(emb, Wxh0, bxh0);
  rec_kernel<<<NCTA, 256, smem_bytes>>>(src, lens, Whh0, Wxh1, bxh1, Whh1);
  fc_kernel<<<dim3(2, Tt), 256>>>(fcw, fcb, (float*)d_out);
}

// round 13
// speedup vs baseline: 1.8574x; 1.3216x over previous
#include <cuda_runtime.h>
#include <cstdint>

#define Bt   128
#define Tt   512
#define Et   256
#define Ht   512
#define VCt  64
#define VPt  128
#define NCTA 128
#define NTHR 512

// ---------------- persistent device scratch ----------------
__device__ float g_P[VCt * Ht];
__device__ float g_h0[2][Ht * Bt];   // [j][b]
__device__ float g_h1[2][Ht * Bt];
__device__ float g_ysT[(size_t)Tt * Ht * Bt];
__device__ unsigned g_count = 0;
__device__ unsigned g_sense = 0;

// ---------------- kernel 1: P = emb_table @ W_xh0 + b_xh0 ----------------
__global__ __launch_bounds__(128) void proj_kernel(
    const float* __restrict__ emb, const float* __restrict__ Wxh0,
    const float* __restrict__ bxh0) {
  __shared__ float esh[Et];
  int v = blockIdx.x;
  for (int i = threadIdx.x; i < Et; i += 128) esh[i] = emb[v * Et + i];
  __syncthreads();
  int j = threadIdx.x + blockIdx.y * 128;
  float s = bxh0[j];
#pragma unroll 8
  for (int e = 0; e < Et; ++e) s = fmaf(esh[e], Wxh0[e * Ht + j], s);
  g_P[v * Ht + j] = s;
}

__device__ __forceinline__ void fma16(float4& a0, float4& a1, float4& a2,
                                      float4& a3, const float4 w,
                                      const float4 hv) {
  a0.x = fmaf(w.x, hv.x, a0.x); a0.y = fmaf(w.x, hv.y, a0.y);
  a0.z = fmaf(w.x, hv.z, a0.z); a0.w = fmaf(w.x, hv.w, a0.w);
  a1.x = fmaf(w.y, hv.x, a1.x); a1.y = fmaf(w.y, hv.y, a1.y);
  a1.z = fmaf(w.y, hv.z, a1.z); a1.w = fmaf(w.y, hv.w, a1.w);
  a2.x = fmaf(w.z, hv.x, a2.x); a2.y = fmaf(w.z, hv.y, a2.y);
  a2.z = fmaf(w.z, hv.z, a2.z); a2.w = fmaf(w.z, hv.w, a2.w);
  a3.x = fmaf(w.w, hv.x, a3.x); a3.y = fmaf(w.w, hv.y, a3.y);
  a3.z = fmaf(w.w, hv.z, a3.z); a3.w = fmaf(w.w, hv.w, a3.w);
}

// ---------------- kernel 2: persistent recurrent kernel ----------------
// 128 CTAs x 512 threads (16 warps). CTA owns cols jb..jb+3 of h0 AND h1.
// Warp s owns k-slice of 32 -> 4 eligible warps per SMSP to hide L2/LDS
// latency. One grid barrier per step (R4's proven counter+sense barrier).
__global__ __launch_bounds__(NTHR, 1) void rec_kernel(
    const int* __restrict__ src, const int* __restrict__ lens,
    const float* __restrict__ Whh0, const float* __restrict__ Wxh1,
    const float* __restrict__ bxh1, const float* __restrict__ Whh1) {
  extern __shared__ char dsm[];
  float4* Wsh0 = (float4*)dsm;         // [512 k]{c0..c3}  8 KB (Whh0)
  float4* Wsh1 = Wsh0 + Ht;            // Wxh1
  float4* Wsh2 = Wsh1 + Ht;            // Whh1
  float4* red4 = Wsh2 + Ht;            // [16 s][8 g][32 bt] 64 KB
  float* Psh = (float*)(red4 + 4096);  // [64 v][4 c]  1 KB

  __shared__ int srcsh[Bt];
  __shared__ int lensh[Bt];
  __shared__ float bsh[4];
  __shared__ unsigned s_sense;

  const int tid = threadIdx.x;
  const int jb = blockIdx.x * 4;

  for (int i = tid; i < Ht * 4; i += NTHR) {
    int k = i >> 2, c = i & 3;
    ((float*)Wsh0)[i] = Whh0[k * Ht + jb + c];
    ((float*)Wsh1)[i] = Wxh1[k * Ht + jb + c];
    ((float*)Wsh2)[i] = Whh1[k * Ht + jb + c];
  }
  for (int i = tid; i < VCt * 4; i += NTHR) {
    int v = i >> 2, c = i & 3;
    Psh[i] = g_P[v * Ht + jb + c];
  }
  if (tid < Bt) lensh[tid] = lens[tid];
  if (tid < 4) bsh[tid] = bxh1[jb + tid];
  // h1(-1) = 0 in buffer 1 (own cols only)
  for (int i = tid; i < 512; i += NTHR) {
    int c = i >> 7, b = i & 127;
    g_h1[1][(jb + c) * Bt + b] = 0.f;
  }
  __syncthreads();
  // prologue: h0(0) = mask0 ? tanh(P[tok0]) : 0  -> buffer 0
  for (int i = tid; i < 512; i += NTHR) {
    int c = i >> 7, b = i & 127;
    int tok = src[b * Tt];
    float a = Psh[tok * 4 + c];
    g_h0[0][(jb + c) * Bt + b] = (0 < lensh[b]) ? tanhf(a) : 0.f;
  }
  if (tid == 0) s_sense = *(volatile unsigned*)&g_sense;
  __syncthreads();

#define GBAR()                                              \
  do {                                                      \
    __syncthreads();                                        \
    if (tid == 0) {                                         \
      unsigned ns = s_sense ^ 1u;                           \
      __threadfence();                                      \
      unsigned old = atomicAdd(&g_count, 1u);               \
      if (old == (unsigned)(NCTA - 1)) {                    \
        g_count = 0u;                                       \
        __threadfence();                                    \
        *(volatile unsigned*)&g_sense = ns;                 \
      } else {                                              \
        while (*(volatile unsigned*)&g_sense != ns)         \
          __nanosleep(20);                                  \
      }                                                     \
      __threadfence();                                      \
      s_sense = ns;                                         \
    }                                                       \
    __syncthreads();                                        \
  } while (0)

  GBAR();  // h0(0), h1(-1) visible everywhere

  const int bt = tid & 31;   // 4 b's: b = 4*bt .. 4*bt+3
  const int s = tid >> 5;    // k-slice of 32 (16 warps)

  for (int t = 0; t < Tt; ++t) {
    const int p = t & 1;
    const float4* H0 = (const float4*)g_h0[p];        // h0(t)
    const float4* H1p = (const float4*)g_h1[p ^ 1];   // h1(t-1)
    float* h0n = g_h0[p ^ 1];                         // h0(t+1)
    float* h1c = g_h1[p];                             // h1(t)

    if (tid < Bt) {
      int tn = (t + 1 < Tt) ? t + 1 : Tt - 1;
      srcsh[tid] = src[tid * Tt + tn];
    }

    // ---- fused GEMMs: accN = h0(t)@Whh0 ; accO = h0(t)@Wxh1 + h1(t-1)@Whh1
    {
      float4 z = make_float4(0, 0, 0, 0);
      float4 n0 = z, n1 = z, n2 = z, n3 = z;
      float4 o0 = z, o1 = z, o2 = z, o3 = z;
#pragma unroll 4
      for (int kk = 0; kk < 32; ++kk) {
        int k = s * 32 + kk;
        float4 ha = H0[k * 32 + bt];
        float4 hb = H1p[k * 32 + bt];
        float4 w0 = Wsh0[k];
        float4 w1 = Wsh1[k];
        float4 w2 = Wsh2[k];
        fma16(n0, n1, n2, n3, w0, ha);
        fma16(o0, o1, o2, o3, w1, ha);
        fma16(o0, o1, o2, o3, w2, hb);
      }
      red4[s * 256 + 0 * 32 + bt] = n0;
      red4[s * 256 + 1 * 32 + bt] = n1;
      red4[s * 256 + 2 * 32 + bt] = n2;
      red4[s * 256 + 3 * 32 + bt] = n3;
      red4[s * 256 + 4 * 32 + bt] = o0;
      red4[s * 256 + 5 * 32 + bt] = o1;
      red4[s * 256 + 6 * 32 + bt] = o2;
      red4[s * 256 + 7 * 32 + bt] = o3;
    }
    __syncthreads();

    // ---- reduce (tid < 256): thread -> group g (phase*4+c), bt2, 4 b's ----
    if (tid < 256) {
      int g = tid >> 5, bt2 = tid & 31;
      int b0 = bt2 * 4;
      float4 sm = red4[g * 32 + bt2];
#pragma unroll
      for (int s2 = 1; s2 < 16; ++s2) {
        float4 r = red4[s2 * 256 + g * 32 + bt2];
        sm.x += r.x; sm.y += r.y; sm.z += r.z; sm.w += r.w;
      }
      int l0 = lensh[b0], l1 = lensh[b0 + 1], l2 = lensh[b0 + 2],
          l3 = lensh[b0 + 3];
      if (g < 4) {  // h0(t+1)
        int c = g;
        sm.x += Psh[srcsh[b0] * 4 + c];
        sm.y += Psh[srcsh[b0 + 1] * 4 + c];
        sm.z += Psh[srcsh[b0 + 2] * 4 + c];
        sm.w += Psh[srcsh[b0 + 3] * 4 + c];
        const float* h0cur = g_h0[p];
        float4 prev = *(const float4*)&h0cur[(jb + c) * Bt + b0];
        float4 nv;
        nv.x = (t + 1 < l0) ? tanhf(sm.x) : prev.x;
        nv.y = (t + 1 < l1) ? tanhf(sm.y) : prev.y;
        nv.z = (t + 1 < l2) ? tanhf(sm.z) : prev.z;
        nv.w = (t + 1 < l3) ? tanhf(sm.w) : prev.w;
        *(float4*)&h0n[(jb + c) * Bt + b0] = nv;
      } else {  // h1(t) + ys(t)
        int c = g - 4;
        float bv = bsh[c];
        sm.x += bv; sm.y += bv; sm.z += bv; sm.w += bv;
        const float* h1prv = g_h1[p ^ 1];
        float4 prev = *(const float4*)&h1prv[(jb + c) * Bt + b0];
        float4 nv;
        nv.x = (t < l0) ? tanhf(sm.x) : prev.x;
        nv.y = (t < l1) ? tanhf(sm.y) : prev.y;
        nv.z = (t < l2) ? tanhf(sm.z) : prev.z;
        nv.w = (t < l3) ? tanhf(sm.w) : prev.w;
        *(float4*)&h1c[(jb + c) * Bt + b0] = nv;
        float* ys = g_ysT + (size_t)t * (Ht * Bt);
        *(float4*)&ys[(jb + c) * Bt + b0] = nv;
      }
    }
    GBAR();  // publish h0(t+1), h1(t), ys(t); protects red/srcsh reuse
  }
#undef GBAR
}

// ---------------- kernel 3: logits = ys @ fc_w + fc_b ----------------
__global__ __launch_bounds__(256) void fc_kernel(const float* __restrict__ fcw,
                                                 const float* __restrict__ fcb,
                                                 float* __restrict__ out) {
  __shared__ float4 Ash[32 * 32];
  __shared__ float4 Bsh[32 * 16];
  const int t = blockIdx.y;
  const int pt = blockIdx.x;
  const int tid = threadIdx.x;
  const int pq = tid & 15;
  const int bq = tid >> 4;
  const float4* ys4 = (const float4*)g_ysT + (size_t)t * (Ht * Bt / 4);
  const float4* w4 = (const float4*)fcw;

  float4 acc[8];
#pragma unroll
  for (int i = 0; i < 8; ++i) acc[i] = make_float4(0, 0, 0, 0);

  for (int k0 = 0; k0 < Ht; k0 += 32) {
#pragma unroll
    for (int i = 0; i < 4; ++i) {
      int idx = tid + i * 256;
      int kk = idx >> 5, b4 = idx & 31;
      Ash[idx] = ys4[(k0 + kk) * 32 + b4];
    }
#pragma unroll
    for (int i = 0; i < 2; ++i) {
      int idx = tid + i * 256;
      int kk = idx >> 4, p4 = idx & 15;
      Bsh[idx] = w4[(k0 + kk) * (VPt / 4) + pt * 16 + p4];
    }
    __syncthreads();
#pragma unroll
    for (int kk = 0; kk < 32; ++kk) {
      float4 wv = Bsh[kk * 16 + pq];
      float4 hA = Ash[kk * 32 + bq * 2];
      float4 hB = Ash[kk * 32 + bq * 2 + 1];
      float hb[8] = {hA.x, hA.y, hA.z, hA.w, hB.x, hB.y, hB.z, hB.w};
#pragma unroll
      for (int i = 0; i < 8; ++i) {
        acc[i].x = fmaf(hb[i], wv.x, acc[i].x);
        acc[i].y = fmaf(hb[i], wv.y, acc[i].y);
        acc[i].z = fmaf(hb[i], wv.z, acc[i].z);
        acc[i].w = fmaf(hb[i], wv.w, acc[i].w);
      }
    }
    __syncthreads();
  }
  float4 bv = ((const float4*)fcb)[pt * 16 + pq];
  float4* out4 = (float4*)out;
#pragma unroll
  for (int i = 0; i < 8; ++i) {
    int b = bq * 8 + i;
    float4 v;
    v.x = acc[i].x + bv.x;
    v.y = acc[i].y + bv.y;
    v.z = acc[i].z + bv.z;
    v.w = acc[i].w + bv.w;
    out4[((size_t)b * Tt + t) * (VPt / 4) + pt * 16 + pq] = v;
  }
}

extern "C" void kernel_launch(void* const* d_in, const int* in_sizes, int n_in,
                              void* d_out, int out_size) {
  const int* src = (const int*)d_in[0];
  const int* lens = (const int*)d_in[1];
  const float* emb = (const float*)d_in[2];
  const float* Wxh0 = (const float*)d_in[3];
  const float* bxh0 = (const float*)d_in[4];
  const float* Whh0 = (const float*)d_in[5];
  const float* Wxh1 = (const float*)d_in[6];
  const float* bxh1 = (const float*)d_in[7];
  const float* Whh1 = (const float*)d_in[8];
  const float* fcw = (const float*)d_in[9];
  const float* fcb = (const float*)d_in[10];

  const int smem_bytes = 3 * 8192 + 65536 + 1024;  // 91136
  cudaFuncSetAttribute(rec_kernel, cudaFuncAttributeMaxDynamicSharedMemorySize,
                       smem_bytes);

  proj_kernel<<<dim3(VCt, 4), 128>>>(emb, Wxh0, bxh0);
  rec_kernel<<<NCTA, NTHR, smem_bytes>>>(src, lens, Whh0, Wxh1, bxh1, Whh1);
  fc_kernel<<<dim3(2, Tt), 256>>>(fcw, fcb, (float*)d_out);
}